// round 1
// baseline (speedup 1.0000x reference)
#include <cuda_runtime.h>
#include <math.h>

#define Bb 32
#define Qq 900
#define Tt 300
#define Cc 256

#define NTH 256
#define NWARP (NTH/32)
#define COLS_PER 4   // ceil(900/256)

// ---- scratch (static device globals; no allocation) ----
__device__ float g_cmatT[(size_t)Bb * Tt * Qq];   // [b][t][q]
__device__ float g_rowmax[Bb * Qq];
__device__ float g_rowsum[Bb * Qq];

// ============================================================
// Kernel 1: per-(b,q) softmax stats: rowmax + sum(exp(x-max))
// one warp per row
// ============================================================
__global__ void row_stats_kernel(const float* __restrict__ logits) {
    int warp_in_blk = threadIdx.x >> 5;
    int lane = threadIdx.x & 31;
    int row = blockIdx.x * (blockDim.x >> 5) + warp_in_blk;
    if (row >= Bb * Qq) return;
    const float* lp = logits + (size_t)row * Cc;

    float m = -INFINITY;
    #pragma unroll
    for (int c = lane; c < Cc; c += 32) m = fmaxf(m, lp[c]);
    #pragma unroll
    for (int o = 16; o; o >>= 1) m = fmaxf(m, __shfl_xor_sync(0xFFFFFFFFu, m, o));

    float s = 0.f;
    #pragma unroll
    for (int c = lane; c < Cc; c += 32) s += expf(lp[c] - m);
    #pragma unroll
    for (int o = 16; o; o >>= 1) s += __shfl_xor_sync(0xFFFFFFFFu, s, o);

    if (lane == 0) { g_rowmax[row] = m; g_rowsum[row] = s; }
}

// ============================================================
// Kernel 2: cost matrix, one block per (b,q), thread t = target
// writes Cmat straight into d_out (layout [b][q][t])
// ============================================================
__global__ void cost_kernel(const float* __restrict__ logits,
                            const float* __restrict__ pboxes,
                            const float* __restrict__ pcut,
                            const int*   __restrict__ tlabels,
                            const float* __restrict__ tboxes,
                            const float* __restrict__ tcut,
                            float* __restrict__ out) {
    int bq = blockIdx.x;               // 0 .. B*Q-1
    int b = bq / Qq;
    int t = threadIdx.x;
    if (t >= Tt) return;

    float px0 = pboxes[bq * 4 + 0];
    float py0 = pboxes[bq * 4 + 1];
    float px1 = pboxes[bq * 4 + 2];
    float py1 = pboxes[bq * 4 + 3];
    float pc  = pcut[bq];
    float rm  = g_rowmax[bq];
    float rs  = g_rowsum[bq];
    float area_p = (px1 - px0) * (py1 - py0);

    int bt = b * Tt + t;
    int lbl = tlabels[bt];
    float logit = logits[(size_t)bq * Cc + lbl];
    float cost_class = -(expf(logit - rm) / rs);

    float tx0 = tboxes[bt * 4 + 0];
    float ty0 = tboxes[bt * 4 + 1];
    float tx1 = tboxes[bt * 4 + 2];
    float ty1 = tboxes[bt * 4 + 3];

    float cost_bbox = fabsf(px0 - tx0) + fabsf(py0 - ty0)
                    + fabsf(px1 - tx1) + fabsf(py1 - ty1);

    float area_t = (tx1 - tx0) * (ty1 - ty0);
    float iw = fmaxf(fminf(px1, tx1) - fmaxf(px0, tx0), 0.f);
    float ih = fmaxf(fminf(py1, ty1) - fmaxf(py0, ty0), 0.f);
    float inter = iw * ih;
    float uni = area_p + area_t - inter;
    float iou = inter / uni;
    float ew = fmaxf(fmaxf(px1, tx1) - fminf(px0, tx0), 0.f);
    float eh = fmaxf(fmaxf(py1, ty1) - fminf(py0, ty0), 0.f);
    float enc = ew * eh;
    float giou = iou - (enc - uni) / enc;

    float cost_cutin = fabsf(pc - tcut[bt]);

    out[(size_t)bq * Tt + t] =
        5.0f * cost_bbox + 1.0f * cost_class - 2.0f * giou + 2.0f * cost_cutin;
}

// ============================================================
// Kernel 3: transpose Cmat[b][q][t] -> g_cmatT[b][t][q]
// ============================================================
__global__ void transpose_kernel(const float* __restrict__ cm) {
    __shared__ float tile[32][33];
    int b  = blockIdx.z;
    int t0 = blockIdx.x * 32;
    int q0 = blockIdx.y * 32;

    for (int r = threadIdx.y; r < 32; r += blockDim.y) {
        int q = q0 + r, t = t0 + threadIdx.x;
        if (q < Qq && t < Tt)
            tile[r][threadIdx.x] = cm[((size_t)b * Qq + q) * Tt + t];
    }
    __syncthreads();
    for (int r = threadIdx.y; r < 32; r += blockDim.y) {
        int t = t0 + r, q = q0 + threadIdx.x;
        if (q < Qq && t < Tt)
            g_cmatT[((size_t)b * Tt + t) * Qq + q] = tile[threadIdx.x][r];
    }
}

// ============================================================
// Kernel 4: Jonker-Volgenant shortest augmenting path.
// One block per batch. cost matrix = Cmat[b].T : rows=targets (300),
// cols=queries (900). Column j owned by thread (j-1)%NTH, slot (j-1)/NTH.
// v, minv, used live in the owner's registers. fp64 throughout (matches
// numpy float64 reference path decisions).
// ============================================================
__global__ void __launch_bounds__(NTH)
solver_kernel(float* __restrict__ out_qidx, float* __restrict__ out_tidx) {
    int b = blockIdx.x;
    const float* costT = g_cmatT + (size_t)b * Tt * Qq;

    __shared__ double u[Tt + 1];
    __shared__ int    p[Qq + 1];
    __shared__ int    way[Qq + 1];
    __shared__ double red_v[NWARP];
    __shared__ int    red_j[NWARP];
    __shared__ double sh_delta;
    __shared__ int    sh_j1;

    int tid = threadIdx.x;

    for (int k = tid; k <= Qq; k += NTH) p[k] = 0;
    for (int k = tid; k <= Tt; k += NTH) u[k] = 0.0;

    double v[COLS_PER];
    double minv[COLS_PER];
    #pragma unroll
    for (int s = 0; s < COLS_PER; s++) v[s] = 0.0;
    __syncthreads();

    const double DINF = (double)INFINITY;

    for (int i = 1; i <= Tt; i++) {
        if (tid == 0) p[0] = i;
        unsigned usedmask = 0;
        #pragma unroll
        for (int s = 0; s < COLS_PER; s++) minv[s] = DINF;
        int j0 = 0;
        __syncthreads();   // p[0]=i and previous augmentation visible

        while (true) {
            // mark j0 used (owner-only state, no sync needed)
            if (j0 > 0) {
                int rel = j0 - 1;
                if ((rel & (NTH - 1)) == tid) usedmask |= 1u << (rel / NTH);
            }
            int i0 = p[j0];
            double ui0 = u[i0];
            const float* crow = costT + (size_t)(i0 - 1) * Qq;

            // scan owned free columns; update minv/way; local argmin
            double lv = DINF; int lj = Qq + 1;
            #pragma unroll
            for (int s = 0; s < COLS_PER; s++) {
                int j = tid + s * NTH + 1;
                if (j <= Qq && !((usedmask >> s) & 1u)) {
                    double cur = (double)crow[j - 1] - ui0 - v[s];
                    if (cur < minv[s]) { minv[s] = cur; way[j] = j0; }
                    if (minv[s] < lv) { lv = minv[s]; lj = j; }
                }
            }
            // lexicographic (value, index) reduction -> matches np.argmin tie-break
            #pragma unroll
            for (int o = 16; o; o >>= 1) {
                double ov = __shfl_down_sync(0xFFFFFFFFu, lv, o);
                int    oj = __shfl_down_sync(0xFFFFFFFFu, lj, o);
                if (ov < lv || (ov == lv && oj < lj)) { lv = ov; lj = oj; }
            }
            if ((tid & 31) == 0) { red_v[tid >> 5] = lv; red_j[tid >> 5] = lj; }
            __syncthreads();
            if (tid == 0) {
                double bv = red_v[0]; int bj = red_j[0];
                #pragma unroll
                for (int w = 1; w < NWARP; w++)
                    if (red_v[w] < bv || (red_v[w] == bv && red_j[w] < bj))
                        { bv = red_v[w]; bj = red_j[w]; }
                sh_delta = bv; sh_j1 = bj;
            }
            __syncthreads();
            double delta = sh_delta;
            int    j1    = sh_j1;

            // potential updates: used cols (+ virtual col 0), distinct rows -> no atomics
            if (tid == 0) u[p[0]] += delta;
            #pragma unroll
            for (int s = 0; s < COLS_PER; s++) {
                int j = tid + s * NTH + 1;
                if (j <= Qq) {
                    if ((usedmask >> s) & 1u) { u[p[j]] += delta; v[s] -= delta; }
                    else                      { minv[s] -= delta; }
                }
            }
            j0 = j1;
            __syncthreads();            // u updates visible before next scan
            if (p[j0] == 0) break;      // p unchanged during the while loop
        }

        // augment along way[] chain
        if (tid == 0) {
            int jj = j0;
            while (jj) { int jn = way[jj]; p[jj] = p[jn]; jj = jn; }
        }
        __syncthreads();
    }

    // q_idx[b][t] = assigned query column; t_idx[b][t] = t
    for (int j = tid + 1; j <= Qq; j += NTH)
        if (p[j] > 0) out_qidx[b * Tt + (p[j] - 1)] = (float)(j - 1);
    for (int t = tid; t < Tt; t += NTH)
        out_tidx[b * Tt + t] = (float)t;
}

// ============================================================
extern "C" void kernel_launch(void* const* d_in, const int* in_sizes, int n_in,
                              void* d_out, int out_size) {
    const float* pred_logits = (const float*)d_in[0];   // B*Q*C f32
    const float* pred_boxes  = (const float*)d_in[1];   // B*Q*4 f32
    const float* pred_cutin  = (const float*)d_in[2];   // B*Q   f32
    const int*   tgt_labels  = (const int*)  d_in[3];   // B*T   i32
    const float* tgt_boxes   = (const float*)d_in[4];   // B*T*4 f32
    const float* tgt_cutin   = (const float*)d_in[5];   // B*T   f32

    float* out = (float*)d_out;
    float* out_cmat = out;                                  // B*Q*T
    float* out_qidx = out + (size_t)Bb * Qq * Tt;           // B*T
    float* out_tidx = out_qidx + (size_t)Bb * Tt;           // B*T

    // 1. softmax row stats (one warp per (b,q) row)
    {
        int rows = Bb * Qq;
        int warps_per_blk = 8;
        int blks = (rows + warps_per_blk - 1) / warps_per_blk;
        row_stats_kernel<<<blks, warps_per_blk * 32>>>(pred_logits);
    }
    // 2. cost matrix -> d_out
    cost_kernel<<<Bb * Qq, 320>>>(pred_logits, pred_boxes, pred_cutin,
                                  tgt_labels, tgt_boxes, tgt_cutin, out_cmat);
    // 3. transpose -> g_cmatT
    {
        dim3 grid((Tt + 31) / 32, (Qq + 31) / 32, Bb);
        dim3 blk(32, 8);
        transpose_kernel<<<grid, blk>>>(out_cmat);
    }
    // 4. LSA, one block per batch
    solver_kernel<<<Bb, NTH>>>(out_qidx, out_tidx);
}

// round 2
// speedup vs baseline: 1.3250x; 1.3250x over previous
#include <cuda_runtime.h>
#include <math.h>

#define Bb 32
#define Qq 900
#define Tt 300
#define Cc 256

#define NTH 128
#define NWARP (NTH/32)
#define COLS_PER 8   // ceil(900/128) -> 8*128=1024 slots cover 900

// ---- scratch (static device globals; no allocation) ----
__device__ float g_cmatT[(size_t)Bb * Tt * Qq];   // [b][t][q]
__device__ float g_rowmax[Bb * Qq];
__device__ float g_rowsum[Bb * Qq];

// ============================================================
// Kernel 1: per-(b,q) softmax stats: rowmax + sum(exp(x-max))
// ============================================================
__global__ void row_stats_kernel(const float* __restrict__ logits) {
    int warp_in_blk = threadIdx.x >> 5;
    int lane = threadIdx.x & 31;
    int row = blockIdx.x * (blockDim.x >> 5) + warp_in_blk;
    if (row >= Bb * Qq) return;
    const float* lp = logits + (size_t)row * Cc;

    float m = -INFINITY;
    #pragma unroll
    for (int c = lane; c < Cc; c += 32) m = fmaxf(m, lp[c]);
    #pragma unroll
    for (int o = 16; o; o >>= 1) m = fmaxf(m, __shfl_xor_sync(0xFFFFFFFFu, m, o));

    float s = 0.f;
    #pragma unroll
    for (int c = lane; c < Cc; c += 32) s += expf(lp[c] - m);
    #pragma unroll
    for (int o = 16; o; o >>= 1) s += __shfl_xor_sync(0xFFFFFFFFu, s, o);

    if (lane == 0) { g_rowmax[row] = m; g_rowsum[row] = s; }
}

// ============================================================
// Kernel 2: cost matrix, one block per (b,q), thread t = target
// ============================================================
__global__ void cost_kernel(const float* __restrict__ logits,
                            const float* __restrict__ pboxes,
                            const float* __restrict__ pcut,
                            const int*   __restrict__ tlabels,
                            const float* __restrict__ tboxes,
                            const float* __restrict__ tcut,
                            float* __restrict__ out) {
    int bq = blockIdx.x;               // 0 .. B*Q-1
    int b = bq / Qq;
    int t = threadIdx.x;
    if (t >= Tt) return;

    float px0 = pboxes[bq * 4 + 0];
    float py0 = pboxes[bq * 4 + 1];
    float px1 = pboxes[bq * 4 + 2];
    float py1 = pboxes[bq * 4 + 3];
    float pc  = pcut[bq];
    float rm  = g_rowmax[bq];
    float rs  = g_rowsum[bq];
    float area_p = (px1 - px0) * (py1 - py0);

    int bt = b * Tt + t;
    int lbl = tlabels[bt];
    float logit = logits[(size_t)bq * Cc + lbl];
    float cost_class = -(expf(logit - rm) / rs);

    float tx0 = tboxes[bt * 4 + 0];
    float ty0 = tboxes[bt * 4 + 1];
    float tx1 = tboxes[bt * 4 + 2];
    float ty1 = tboxes[bt * 4 + 3];

    float cost_bbox = fabsf(px0 - tx0) + fabsf(py0 - ty0)
                    + fabsf(px1 - tx1) + fabsf(py1 - ty1);

    float area_t = (tx1 - tx0) * (ty1 - ty0);
    float iw = fmaxf(fminf(px1, tx1) - fmaxf(px0, tx0), 0.f);
    float ih = fmaxf(fminf(py1, ty1) - fmaxf(py0, ty0), 0.f);
    float inter = iw * ih;
    float uni = area_p + area_t - inter;
    float iou = inter / uni;
    float ew = fmaxf(fmaxf(px1, tx1) - fminf(px0, tx0), 0.f);
    float eh = fmaxf(fmaxf(py1, ty1) - fminf(py0, ty0), 0.f);
    float enc = ew * eh;
    float giou = iou - (enc - uni) / enc;

    float cost_cutin = fabsf(pc - tcut[bt]);

    out[(size_t)bq * Tt + t] =
        5.0f * cost_bbox + 1.0f * cost_class - 2.0f * giou + 2.0f * cost_cutin;
}

// ============================================================
// Kernel 3: transpose Cmat[b][q][t] -> g_cmatT[b][t][q]
// ============================================================
__global__ void transpose_kernel(const float* __restrict__ cm) {
    __shared__ float tile[32][33];
    int b  = blockIdx.z;
    int t0 = blockIdx.x * 32;
    int q0 = blockIdx.y * 32;

    for (int r = threadIdx.y; r < 32; r += blockDim.y) {
        int q = q0 + r, t = t0 + threadIdx.x;
        if (q < Qq && t < Tt)
            tile[r][threadIdx.x] = cm[((size_t)b * Qq + q) * Tt + t];
    }
    __syncthreads();
    for (int r = threadIdx.y; r < 32; r += blockDim.y) {
        int t = t0 + r, q = q0 + threadIdx.x;
        if (q < Qq && t < Tt)
            g_cmatT[((size_t)b * Tt + t) * Qq + q] = tile[threadIdx.x][r];
    }
}

// ============================================================
// Kernel 4: Jonker-Volgenant, single-barrier inner step.
// One block/batch, 128 threads, column j owned by thread (j-1)%128,
// slot (j-1)/128. v, minv, used, cost-row prefetch live in the
// owner's registers. fp64 everywhere, same op order as numpy ref.
//
// Race-freedom of the single barrier per step (barrier A, after the
// per-warp minima are written):
//  - scan at step m reads u[i0_m] = u[p[j1_{m-1}]]; step m-1's update
//    touched only u[i] and u[p[j]] for j in used(m-1), and j1 was not
//    yet used => disjoint row (p injective) => no race.
//  - red_v/red_j are double-buffered by step parity; with one barrier
//    per step, concurrent threads span at most adjacent steps.
//  - way[] is owner-written during scans, read only by tid0 after the
//    last barrier A of the augmentation. p[] is stable within an
//    augmentation; tid0's augment writes are fenced by the outer
//    __syncthreads before the next row starts.
// ============================================================
__global__ void __launch_bounds__(NTH)
solver_kernel(float* __restrict__ out_qidx, float* __restrict__ out_tidx) {
    int b = blockIdx.x;
    const float* costT = g_cmatT + (size_t)b * Tt * Qq;

    __shared__ double u[Tt + 1];
    __shared__ int    p[Qq + 1];
    __shared__ int    way[Qq + 1];
    __shared__ double red_v[2][NWARP];
    __shared__ int    red_j[2][NWARP];

    const int tid  = threadIdx.x;
    const int lane = tid & 31;
    const int wrp  = tid >> 5;

    for (int k = tid; k <= Qq; k += NTH) p[k] = 0;
    for (int k = tid; k <= Tt; k += NTH) u[k] = 0.0;

    double v[COLS_PER];
    #pragma unroll
    for (int s = 0; s < COLS_PER; s++) v[s] = 0.0;
    __syncthreads();

    const double DINF = (double)INFINITY;

    for (int i = 1; i <= Tt; i++) {
        if (tid == 0) p[0] = i;
        unsigned usedmask = 0;
        double minv[COLS_PER];
        #pragma unroll
        for (int s = 0; s < COLS_PER; s++) minv[s] = DINF;

        // prefetch cost row (i-1) for the first scan
        float cpre[COLS_PER];
        #pragma unroll
        for (int s = 0; s < COLS_PER; s++) {
            int j = tid + s * NTH + 1;
            if (j <= Qq) cpre[s] = __ldg(&costT[(size_t)(i - 1) * Qq + (j - 1)]);
        }

        int j0 = 0, i0 = i, parity = 0;
        int j1 = 0;

        while (true) {
            // mark j0 used (owner-local)
            if (j0 > 0) {
                int rel = j0 - 1;
                if ((rel & (NTH - 1)) == tid) usedmask |= 1u << (rel >> 7);
            }
            double ui0 = u[i0];

            // scan owned free columns (cost already in registers)
            double lv = DINF; int lj = 0x7FFFFFFF;
            #pragma unroll
            for (int s = 0; s < COLS_PER; s++) {
                int j = tid + s * NTH + 1;
                if (j <= Qq && !((usedmask >> s) & 1u)) {
                    double cur = (double)cpre[s] - ui0 - v[s];
                    if (cur < minv[s]) { minv[s] = cur; way[j] = j0; }
                    if (minv[s] < lv) { lv = minv[s]; lj = j; }
                }
            }

            // warp reduce: value-only butterfly, then min index among ties
            double wv = lv;
            #pragma unroll
            for (int o = 16; o; o >>= 1) {
                double ov = __shfl_xor_sync(0xFFFFFFFFu, wv, o);
                wv = fmin(wv, ov);
            }
            int wj = __reduce_min_sync(0xFFFFFFFFu, (lv == wv) ? lj : 0x7FFFFFFF);
            if (lane == 0) { red_v[parity][wrp] = wv; red_j[parity][wrp] = wj; }
            __syncthreads();   // the ONLY barrier in the step

            // broadcast lexicographic min over 4 warp results (all threads)
            double d0 = red_v[parity][0], d1 = red_v[parity][1];
            double d2 = red_v[parity][2], d3 = red_v[parity][3];
            int    e0 = red_j[parity][0], e1 = red_j[parity][1];
            int    e2 = red_j[parity][2], e3 = red_j[parity][3];
            double da; int ea;
            if (d1 < d0 || (d1 == d0 && e1 < e0)) { da = d1; ea = e1; } else { da = d0; ea = e0; }
            double db; int eb;
            if (d3 < d2 || (d3 == d2 && e3 < e2)) { db = d3; eb = e3; } else { db = d2; eb = e2; }
            double delta; 
            if (db < da || (db == da && eb < ea)) { delta = db; j1 = eb; } else { delta = da; j1 = ea; }

            // next row + prefetch its cost values (hides L2 behind update)
            i0 = p[j1];
            if (i0 > 0) {
                #pragma unroll
                for (int s = 0; s < COLS_PER; s++) {
                    int j = tid + s * NTH + 1;
                    if (j <= Qq) cpre[s] = __ldg(&costT[(size_t)(i0 - 1) * Qq + (j - 1)]);
                }
            }

            // potential updates (numpy does this before the break check too)
            if (tid == 0) u[i] += delta;          // u[p[0]] += delta
            #pragma unroll
            for (int s = 0; s < COLS_PER; s++) {
                int j = tid + s * NTH + 1;
                if (j <= Qq) {
                    if ((usedmask >> s) & 1u) { u[p[j]] += delta; v[s] -= delta; }
                    else                      { minv[s] -= delta; }
                }
            }

            if (i0 == 0) break;
            j0 = j1;
            parity ^= 1;
        }

        // augment along way[] chain
        if (tid == 0) {
            int jj = j1;
            while (jj) { int jn = way[jj]; p[jj] = p[jn]; jj = jn; }
        }
        __syncthreads();
    }

    for (int j = tid + 1; j <= Qq; j += NTH)
        if (p[j] > 0) out_qidx[b * Tt + (p[j] - 1)] = (float)(j - 1);
    for (int t = tid; t < Tt; t += NTH)
        out_tidx[b * Tt + t] = (float)t;
}

// ============================================================
extern "C" void kernel_launch(void* const* d_in, const int* in_sizes, int n_in,
                              void* d_out, int out_size) {
    const float* pred_logits = (const float*)d_in[0];   // B*Q*C f32
    const float* pred_boxes  = (const float*)d_in[1];   // B*Q*4 f32
    const float* pred_cutin  = (const float*)d_in[2];   // B*Q   f32
    const int*   tgt_labels  = (const int*)  d_in[3];   // B*T   i32
    const float* tgt_boxes   = (const float*)d_in[4];   // B*T*4 f32
    const float* tgt_cutin   = (const float*)d_in[5];   // B*T   f32

    float* out = (float*)d_out;
    float* out_cmat = out;                                  // B*Q*T
    float* out_qidx = out + (size_t)Bb * Qq * Tt;           // B*T
    float* out_tidx = out_qidx + (size_t)Bb * Tt;           // B*T

    // 1. softmax row stats
    {
        int rows = Bb * Qq;
        int warps_per_blk = 8;
        int blks = (rows + warps_per_blk - 1) / warps_per_blk;
        row_stats_kernel<<<blks, warps_per_blk * 32>>>(pred_logits);
    }
    // 2. cost matrix -> d_out
    cost_kernel<<<Bb * Qq, 320>>>(pred_logits, pred_boxes, pred_cutin,
                                  tgt_labels, tgt_boxes, tgt_cutin, out_cmat);
    // 3. transpose -> g_cmatT
    {
        dim3 grid((Tt + 31) / 32, (Qq + 31) / 32, Bb);
        dim3 blk(32, 8);
        transpose_kernel<<<grid, blk>>>(out_cmat);
    }
    // 4. LSA, one block per batch
    solver_kernel<<<Bb, NTH>>>(out_qidx, out_tidx);
}